// round 5
// baseline (speedup 1.0000x reference)
#include <cuda_runtime.h>
#include <cuda_bf16.h>
#include <mma.h>
#include <math.h>
#include <stdint.h>

using namespace nvcuda;

// Problem constants
#define B_ 8
#define S_ 8192
#define D_ 512
#define C_ 512
#define H_ 8
#define HD_ 64
#define L_ 2
#define DFF_ 2048
#define M_ (B_ * C_)          // 4096
#define QKV3D (3 * D_)        // 1536

typedef __nv_bfloat16 bf16;
typedef long long ll;

// plane sizes (elements)
#define XS_PL   (M_ * D_)          // 2097152
#define QKVS_PL (M_ * QKV3D)      // 6291456
#define PS_PL   (B_ * H_ * C_ * C_) // 16777216
#define ATT_PL  (M_ * D_)
#define FFS_PL  (M_ * DFF_)        // 8388608
#define WQKV_PL (L_ * QKV3D * D_)  // 1572864
#define WOUT_PL (L_ * D_ * D_)     // 524288
#define WFF1_PL (L_ * DFF_ * D_)   // 2097152
#define WFF2_PL (L_ * D_ * DFF_)   // 2097152

// ------------------------- scratch (device globals) -------------------------
__device__ float g_x[M_ * D_];
__device__ float g_proj[M_ * D_];
__device__ float g_scores[PS_PL];
__device__ float g_y[M_ * D_];
__device__ bf16 g_xs[2 * XS_PL];
__device__ bf16 g_qkvs[2 * QKVS_PL];
__device__ bf16 g_ps[2 * PS_PL];
__device__ bf16 g_attns[2 * ATT_PL];
__device__ bf16 g_ffs[2 * FFS_PL];
__device__ bf16 g_wqkv[2 * WQKV_PL];
__device__ bf16 g_wout[2 * WOUT_PL];
__device__ bf16 g_wff1[2 * WFF1_PL];
__device__ bf16 g_wff2[2 * WFF2_PL];

__device__ __forceinline__ void cvt_hilo(float x, bf16& h, bf16& l) {
    h = __float2bfloat16(x);
    l = __float2bfloat16(x - __bfloat162float(h));
}
__device__ __forceinline__ uint32_t smem_u32(const void* p) {
    uint32_t a;
    asm("{ .reg .u64 t; cvta.to.shared.u64 t, %1; cvt.u32.u64 %0, t; }"
        : "=r"(a) : "l"(p));
    return a;
}
__device__ __forceinline__ void cpa16(uint32_t dst, const void* src) {
    asm volatile("cp.async.cg.shared.global [%0], [%1], 16;" :: "r"(dst), "l"(src));
}
#define CPA_COMMIT() asm volatile("cp.async.commit_group;" ::: "memory")
#define CPA_WAIT(n)  asm volatile("cp.async.wait_group %0;" :: "n"(n) : "memory")

// store float4 as split bf16 (hi at p, lo at p+plane); elem offset 4-aligned
__device__ __forceinline__ void store_split4(bf16* p, ll plane, float4 v) {
    bf16 h0, h1, h2, h3, l0, l1, l2, l3;
    cvt_hilo(v.x, h0, l0); cvt_hilo(v.y, h1, l1);
    cvt_hilo(v.z, h2, l2); cvt_hilo(v.w, h3, l3);
    __nv_bfloat162 a, b;
    a.x = h0; a.y = h1; b.x = h2; b.y = h3;
    *(__nv_bfloat162*)(p) = a; *(__nv_bfloat162*)(p + 2) = b;
    a.x = l0; a.y = l1; b.x = l2; b.y = l3;
    *(__nv_bfloat162*)(p + plane) = a; *(__nv_bfloat162*)(p + plane + 2) = b;
}

// ------------------- weight pre-split: fp32 -> bf16 hi/lo planes -------------
__global__ void split_kernel(const float* __restrict__ src, bf16* __restrict__ dst,
                             ll plane, int n4) {
    int i = blockIdx.x * 256 + threadIdx.x;
    if (i >= n4) return;
    float4 v = ((const float4*)src)[i];
    store_split4(dst + (ll)i * 4, plane, v);
}

// ----------------------- pipelined split-bf16 GEMM ---------------------------
// C[M,N] = A[M,K] @ B + bias. A,B pre-split bf16 (hi plane + lo plane at +plane).
// 3-term: Ah*Bh + Ah*Bl + Al*Bh. BM=128, BK=64 fp-K per chunk, double buffered.
// KN=0: B[n][k] rows; KN=1: B[k][n] (transpose-staged, BN=64 only).
// Output: Cf (fp32) if non-null else split bf16 to Ch (+cPlane).
#define LDS_ 136           // smem row stride in bf16: 64 hi | 64 lo | 8 pad

template<int BN, int KN>
__global__ void __launch_bounds__(256)
gemm_split(const bf16* __restrict__ A, ll aPlane, int lda,
           const bf16* __restrict__ Bm, ll bPlane, int ldb,
           const float* __restrict__ bias,
           float* __restrict__ Cf, bf16* __restrict__ Ch, ll cPlane,
           int ldc, int K, int relu,
           ll sAhi, ll sAlo, ll sBhi, ll sBlo, ll sChi, ll sClo)
{
    extern __shared__ char sm[];
    constexpr int ASZ = 128 * 272;          // bytes per A stage
    constexpr int BSZ = BN * 272;
    constexpr int STG = ASZ + BSZ;
    constexpr int MW = (BN == 128) ? 2 : 4; // warps along M
    constexpr int NW = 8 / MW;
    constexpr int IT = 128 / (MW * 16);     // m frags per warp
    constexpr int JT = BN / (NW * 16);      // n frags per warp
    constexpr int LDC_S = BN + 4;

    float* biass = (float*)(sm + 2 * STG);
    const int tid = threadIdx.x;
    const int wid = tid >> 5;
    const int warp_m = wid % MW;
    const int warp_n = wid / MW;
    const int z = blockIdx.z;
    const ll offA = (ll)(z >> 3) * sAhi + (ll)(z & 7) * sAlo;
    const ll offB = (ll)(z >> 3) * sBhi + (ll)(z & 7) * sBlo;
    const ll offC = (ll)(z >> 3) * sChi + (ll)(z & 7) * sClo;
    const int row0 = blockIdx.y * 128;
    const int n0 = blockIdx.x * BN;
    const bf16* Ab = A + offA + (ll)row0 * lda;   // hi base; lo = +aPlane
    const bf16* Bb = Bm + offB;
    const uint32_t sb = smem_u32(sm);

    if (tid < BN) biass[tid] = bias ? bias[n0 + tid] : 0.f;

    wmma::fragment<wmma::accumulator, 16, 16, 16, float> acc[IT][JT];
#pragma unroll
    for (int i = 0; i < IT; i++)
#pragma unroll
        for (int j = 0; j < JT; j++) wmma::fill_fragment(acc[i][j], 0.f);

    const int nch = K >> 6;

    // ---- staging ----
    auto stage = [&](int ck, int buf) {
        const int k0 = ck << 6;
        uint32_t base = sb + buf * STG;
        // A: 128 rows x (8 hi + 8 lo) 16B segs = 2048 -> 8 per thread
#pragma unroll
        for (int t = 0; t < 8; t++) {
            int lin = tid + (t << 8);
            int r = lin >> 4;
            int s = lin & 15;
            const bf16* src = Ab + (s < 8 ? 0 : aPlane) + (ll)r * lda + k0 + (s & 7) * 8;
            cpa16(base + r * 272 + (s < 8 ? 0 : 128) + (s & 7) * 16, src);
        }
        if (KN == 0) {
            constexpr int BT = (BN * 16) / 256;   // 8 or 4
#pragma unroll
            for (int t = 0; t < BT; t++) {
                int lin = tid + (t << 8);
                int r = lin >> 4;
                int s = lin & 15;
                const bf16* src = Bb + (s < 8 ? 0 : bPlane) + (ll)(n0 + r) * ldb + k0 + (s & 7) * 8;
                cpa16(base + ASZ + r * 272 + (s < 8 ? 0 : 128) + (s & 7) * 16, src);
            }
        } else {
            // B[k][n] transpose staging (BN==64): 64 keys x 64 dims, hi+lo
            bf16* Bsm = (bf16*)(sm + buf * STG + ASZ);
#pragma unroll
            for (int t = 0; t < 2; t++) {
                int lin = tid + (t << 8);
                int key = lin >> 3;
                int s = lin & 7;
                const bf16* srow = Bb + (ll)(k0 + key) * ldb + n0 + s * 8;
                uint4 hv = *(const uint4*)(srow);
                uint4 lv = *(const uint4*)(srow + bPlane);
                const bf16* hp = (const bf16*)&hv;
                const bf16* lp = (const bf16*)&lv;
#pragma unroll
                for (int j = 0; j < 8; j++) {
                    Bsm[(s * 8 + j) * LDS_ + key]      = hp[j];
                    Bsm[(s * 8 + j) * LDS_ + 64 + key] = lp[j];
                }
            }
        }
    };

    auto compute = [&](int buf) {
        const bf16* As_ = (const bf16*)(sm + buf * STG) + (warp_m * IT * 16) * LDS_;
        const bf16* Bs_ = (const bf16*)(sm + buf * STG + ASZ) + (warp_n * JT * 16) * LDS_;
#pragma unroll
        for (int ks = 0; ks < 64; ks += 16) {
            wmma::fragment<wmma::matrix_a, 16, 16, 16, bf16, wmma::row_major> ah[IT], al[IT];
            wmma::fragment<wmma::matrix_b, 16, 16, 16, bf16, wmma::col_major> bh[JT], bl[JT];
#pragma unroll
            for (int i = 0; i < IT; i++) {
                wmma::load_matrix_sync(ah[i], As_ + (i * 16) * LDS_ + ks, LDS_);
                wmma::load_matrix_sync(al[i], As_ + (i * 16) * LDS_ + 64 + ks, LDS_);
            }
#pragma unroll
            for (int j = 0; j < JT; j++) {
                wmma::load_matrix_sync(bh[j], Bs_ + (j * 16) * LDS_ + ks, LDS_);
                wmma::load_matrix_sync(bl[j], Bs_ + (j * 16) * LDS_ + 64 + ks, LDS_);
            }
#pragma unroll
            for (int i = 0; i < IT; i++)
#pragma unroll
                for (int j = 0; j < JT; j++) {
                    wmma::mma_sync(acc[i][j], ah[i], bh[j], acc[i][j]);
                    wmma::mma_sync(acc[i][j], ah[i], bl[j], acc[i][j]);
                    wmma::mma_sync(acc[i][j], al[i], bh[j], acc[i][j]);
                }
        }
    };

    stage(0, 0);
    CPA_COMMIT();
    for (int ck = 0; ck < nch; ck++) {
        if (ck + 1 < nch) {
            stage(ck + 1, (ck + 1) & 1);
            CPA_COMMIT();
            CPA_WAIT(1);
        } else {
            CPA_WAIT(0);
        }
        __syncthreads();
        compute(ck & 1);
        __syncthreads();
    }

    // ---- epilogue (reuse stage smem as fp32 Cs) ----
    float* Csm = (float*)sm;
#pragma unroll
    for (int i = 0; i < IT; i++)
#pragma unroll
        for (int j = 0; j < JT; j++)
            wmma::store_matrix_sync(
                Csm + (warp_m * IT * 16 + i * 16) * LDC_S + warp_n * JT * 16 + j * 16,
                acc[i][j], LDC_S, wmma::mem_row_major);
    __syncthreads();

    const int r = tid >> 1;
    const int c0 = (tid & 1) * (BN / 2);
    const ll rowoff = offC + (ll)(row0 + r) * ldc + n0;
#pragma unroll
    for (int cc = c0; cc < c0 + BN / 2; cc += 4) {
        float4 v = *(float4*)(Csm + r * LDC_S + cc);
        v.x += biass[cc + 0]; v.y += biass[cc + 1];
        v.z += biass[cc + 2]; v.w += biass[cc + 3];
        if (relu) {
            v.x = fmaxf(v.x, 0.f); v.y = fmaxf(v.y, 0.f);
            v.z = fmaxf(v.z, 0.f); v.w = fmaxf(v.w, 0.f);
        }
        if (Cf) *(float4*)(Cf + rowoff + cc) = v;
        else    store_split4(Ch + rowoff + cc, cPlane, v);
    }
}

// ------------------------------- pooling ------------------------------------
__global__ void pool_kernel(const float* __restrict__ tokens,
                            const int* __restrict__ seg,
                            float* __restrict__ x, bf16* __restrict__ xs) {
    int c = blockIdx.x;
    int b = blockIdx.y;
    const int* ids = seg + (size_t)b * S_;
    int lo = 0, hi = S_;
    while (lo < hi) { int mid = (lo + hi) >> 1; if (ids[mid] < c) lo = mid + 1; else hi = mid; }
    int s0 = lo;
    hi = S_;
    while (lo < hi) { int mid = (lo + hi) >> 1; if (ids[mid] < c + 1) lo = mid + 1; else hi = mid; }
    int s1 = lo;
    float inv = 1.0f / (float)(s1 - s0);

    int d = threadIdx.x;
    float sum0 = 0.f, sum1 = 0.f;
    for (int s = s0; s < s1; s++) {
        const float* t = tokens + ((size_t)b * S_ + s) * D_;
        sum0 += t[d];
        sum1 += t[d + 256];
    }
    ll off = ((ll)b * C_ + c) * D_;
    float v0 = sum0 * inv, v1 = sum1 * inv;
    g_x[off + d] = v0;  g_x[off + d + 256] = v1;
    x = x; // silence unused (x==g_x by construction)
    bf16 h, l2;
    cvt_hilo(v0, h, l2);
    xs[off + d] = h; xs[XS_PL + off + d] = l2;
    cvt_hilo(v1, h, l2);
    xs[off + d + 256] = h; xs[XS_PL + off + d + 256] = l2;
}

// ------------------------------- softmax ------------------------------------
// scores fp32 -> P split bf16 planes (applies 1/8 scale).
__global__ void softmax_kernel(const float* __restrict__ s, bf16* __restrict__ ps) {
    ll base = (ll)blockIdx.x * 512;
    int tid = threadIdx.x;             // 128
    int lane = tid & 31, warp = tid >> 5;
    float4 v = *(const float4*)(s + base + tid * 4);
    v.x *= 0.125f; v.y *= 0.125f; v.z *= 0.125f; v.w *= 0.125f;

    __shared__ float red[4];
    float mx = fmaxf(fmaxf(v.x, v.y), fmaxf(v.z, v.w));
#pragma unroll
    for (int o = 16; o >= 1; o >>= 1) mx = fmaxf(mx, __shfl_xor_sync(0xffffffffu, mx, o));
    if (lane == 0) red[warp] = mx;
    __syncthreads();
    mx = fmaxf(fmaxf(red[0], red[1]), fmaxf(red[2], red[3]));

    float4 e;
    e.x = __expf(v.x - mx); e.y = __expf(v.y - mx);
    e.z = __expf(v.z - mx); e.w = __expf(v.w - mx);
    float sum = e.x + e.y + e.z + e.w;
#pragma unroll
    for (int o = 16; o >= 1; o >>= 1) sum += __shfl_xor_sync(0xffffffffu, sum, o);
    __syncthreads();
    if (lane == 0) red[warp] = sum;
    __syncthreads();
    float inv = 1.0f / (red[0] + red[1] + red[2] + red[3]);
    e.x *= inv; e.y *= inv; e.z *= inv; e.w *= inv;
    store_split4(ps + base + tid * 4, PS_PL, e);
}

// -------------------------- residual + layernorm ----------------------------
// out = LN(xin + res) * w + b. Writes fp32 out and optionally split bf16.
__global__ void ln_kernel(const float* __restrict__ xin,
                          const float* __restrict__ res,
                          const float* __restrict__ w,
                          const float* __restrict__ bv,
                          float* __restrict__ out, bf16* __restrict__ outs) {
    int row = blockIdx.x;
    int tid = threadIdx.x;
    size_t off = (size_t)row * D_;
    float v0 = xin[off + tid];
    float v1 = xin[off + tid + 256];
    if (res) { v0 += res[off + tid]; v1 += res[off + tid + 256]; }

    __shared__ float red[8];
    __shared__ float sbc;
    int lane = tid & 31, warp = tid >> 5;

    float s = v0 + v1;
#pragma unroll
    for (int o2 = 16; o2 >= 1; o2 >>= 1) s += __shfl_xor_sync(0xffffffffu, s, o2);
    if (lane == 0) red[warp] = s;
    __syncthreads();
    if (tid == 0) {
        float t = 0.f;
#pragma unroll
        for (int i = 0; i < 8; i++) t += red[i];
        sbc = t * (1.0f / D_);
    }
    __syncthreads();
    float mu = sbc;
    float d0 = v0 - mu, d1 = v1 - mu;
    s = d0 * d0 + d1 * d1;
    __syncthreads();
#pragma unroll
    for (int o2 = 16; o2 >= 1; o2 >>= 1) s += __shfl_xor_sync(0xffffffffu, s, o2);
    if (lane == 0) red[warp] = s;
    __syncthreads();
    if (tid == 0) {
        float t = 0.f;
#pragma unroll
        for (int i = 0; i < 8; i++) t += red[i];
        sbc = rsqrtf(t * (1.0f / D_) + 1e-5f);
    }
    __syncthreads();
    float inv = sbc;
    float r0 = d0 * inv * w[tid] + bv[tid];
    float r1 = d1 * inv * w[tid + 256] + bv[tid + 256];
    out[off + tid] = r0;
    out[off + tid + 256] = r1;
    if (outs) {
        bf16 h, l2;
        cvt_hilo(r0, h, l2);
        outs[off + tid] = h; outs[XS_PL + off + tid] = l2;
        cvt_hilo(r1, h, l2);
        outs[off + tid + 256] = h; outs[XS_PL + off + tid + 256] = l2;
    }
}

// ------------------------------- expand -------------------------------------
__global__ void expand_kernel(const float* __restrict__ y,
                              const int* __restrict__ seg,
                              float* __restrict__ out) {
    int bs = blockIdx.x;
    int b = bs >> 13;
    int c = seg[bs];
    const float4* src = (const float4*)(y + ((size_t)b * C_ + c) * D_);
    float4* dst = (float4*)(out + (size_t)bs * D_);
    dst[threadIdx.x] = src[threadIdx.x];
}

// ------------------------------ launcher ------------------------------------
extern "C" void kernel_launch(void* const* d_in, const int* in_sizes, int n_in,
                              void* d_out, int out_size) {
    const float* tokens = (const float*)d_in[0];
    const int*   seg    = (const int*)d_in[1];
    const float* qkv_w  = (const float*)d_in[2];
    const float* qkv_b  = (const float*)d_in[3];
    const float* out_w  = (const float*)d_in[4];
    const float* out_b  = (const float*)d_in[5];
    const float* ln1_w  = (const float*)d_in[6];
    const float* ln1_b  = (const float*)d_in[7];
    const float* ln2_w  = (const float*)d_in[8];
    const float* ln2_b  = (const float*)d_in[9];
    const float* ff1_w  = (const float*)d_in[10];
    const float* ff1_b  = (const float*)d_in[11];
    const float* ff2_w  = (const float*)d_in[12];
    const float* ff2_b  = (const float*)d_in[13];
    const float* fln_w  = (const float*)d_in[14];
    const float* fln_b  = (const float*)d_in[15];
    float* out = (float*)d_out;

    float *x, *proj, *scores, *y;
    bf16 *xs, *qkvs, *ps, *attns, *ffs, *wqkv, *wout, *wff1, *wff2;
    cudaGetSymbolAddress((void**)&x, g_x);
    cudaGetSymbolAddress((void**)&proj, g_proj);
    cudaGetSymbolAddress((void**)&scores, g_scores);
    cudaGetSymbolAddress((void**)&y, g_y);
    cudaGetSymbolAddress((void**)&xs, g_xs);
    cudaGetSymbolAddress((void**)&qkvs, g_qkvs);
    cudaGetSymbolAddress((void**)&ps, g_ps);
    cudaGetSymbolAddress((void**)&attns, g_attns);
    cudaGetSymbolAddress((void**)&ffs, g_ffs);
    cudaGetSymbolAddress((void**)&wqkv, g_wqkv);
    cudaGetSymbolAddress((void**)&wout, g_wout);
    cudaGetSymbolAddress((void**)&wff1, g_wff1);
    cudaGetSymbolAddress((void**)&wff2, g_wff2);

    const int SM128 = 2 * (128 + 128) * 272 + 128 * 4;   // 139776
    const int SM64  = 2 * (128 + 64) * 272 + 64 * 4;     // 104704
    cudaFuncSetAttribute(gemm_split<128, 0>,
                         cudaFuncAttributeMaxDynamicSharedMemorySize, SM128);
    cudaFuncSetAttribute(gemm_split<64, 1>,
                         cudaFuncAttributeMaxDynamicSharedMemorySize, SM64);

    // weight pre-split
    split_kernel<<<WQKV_PL / 1024, 256>>>(qkv_w, wqkv, WQKV_PL, WQKV_PL / 4);
    split_kernel<<<WOUT_PL / 1024, 256>>>(out_w, wout, WOUT_PL, WOUT_PL / 4);
    split_kernel<<<WFF1_PL / 1024, 256>>>(ff1_w, wff1, WFF1_PL, WFF1_PL / 4);
    split_kernel<<<WFF2_PL / 1024, 256>>>(ff2_w, wff2, WFF2_PL, WFF2_PL / 4);

    pool_kernel<<<dim3(C_, B_), 256>>>(tokens, seg, x, xs);

    const ll CC = (ll)C_ * C_;
    const ll CQ = (ll)C_ * QKV3D;

    for (int l = 0; l < L_; l++) {
        // QKV proj: [4096,512] @ Wqkv^T -> split qkvs
        gemm_split<128, 0><<<dim3(QKV3D / 128, M_ / 128, 1), 256, SM128>>>(
            xs, XS_PL, D_, wqkv + (ll)l * QKV3D * D_, WQKV_PL, D_,
            qkv_b + (ll)l * QKV3D, nullptr, qkvs, QKVS_PL, QKV3D, D_, 0,
            0, 0, 0, 0, 0, 0);

        // scores = Q @ K^T (64 batches, M=N=512, K=64) -> fp32
        gemm_split<128, 0><<<dim3(C_ / 128, C_ / 128, B_ * H_), 256, SM128>>>(
            qkvs, QKVS_PL, QKV3D, qkvs + D_, QKVS_PL, QKV3D,
            nullptr, scores, nullptr, 0, C_, HD_, 0,
            CQ, HD_, CQ, HD_, (ll)H_ * CC, CC);

        softmax_kernel<<<B_ * H_ * C_, 128>>>(scores, ps);

        // attn out = P @ V (64 batches, M=512, N=64, K=512; B is [k][n]) -> split attns
        gemm_split<64, 1><<<dim3(1, C_ / 128, B_ * H_), 256, SM64>>>(
            ps, PS_PL, C_, qkvs + 2 * D_, QKVS_PL, QKV3D,
            nullptr, nullptr, attns, ATT_PL, D_, C_, 0,
            (ll)H_ * CC, CC, CQ, HD_, (ll)C_ * D_, HD_);

        // out proj -> fp32 proj
        gemm_split<128, 0><<<dim3(D_ / 128, M_ / 128, 1), 256, SM128>>>(
            attns, ATT_PL, D_, wout + (ll)l * D_ * D_, WOUT_PL, D_,
            out_b + (ll)l * D_, proj, nullptr, 0, D_, D_, 0,
            0, 0, 0, 0, 0, 0);
        ln_kernel<<<M_, 256>>>(x, proj, ln1_w + (ll)l * D_, ln1_b + (ll)l * D_, x, xs);

        // FF1 (relu) -> split ffs
        gemm_split<128, 0><<<dim3(DFF_ / 128, M_ / 128, 1), 256, SM128>>>(
            xs, XS_PL, D_, wff1 + (ll)l * DFF_ * D_, WFF1_PL, D_,
            ff1_b + (ll)l * DFF_, nullptr, ffs, FFS_PL, DFF_, D_, 1,
            0, 0, 0, 0, 0, 0);
        // FF2 -> fp32 proj
        gemm_split<128, 0><<<dim3(D_ / 128, M_ / 128, 1), 256, SM128>>>(
            ffs, FFS_PL, DFF_, wff2 + (ll)l * D_ * DFF_, WFF2_PL, DFF_,
            ff2_b + (ll)l * D_, proj, nullptr, 0, D_, DFF_, 0,
            0, 0, 0, 0, 0, 0);
        ln_kernel<<<M_, 256>>>(x, proj, ln2_w + (ll)l * D_, ln2_b + (ll)l * D_, x, xs);
    }

    ln_kernel<<<M_, 256>>>(x, nullptr, fln_w, fln_b, y, nullptr);
    expand_kernel<<<B_ * S_, 128>>>(y, seg, out);
}